// round 8
// baseline (speedup 1.0000x reference)
#include <cuda_runtime.h>
#include <math.h>
#include <stdint.h>

#define BB 4
#define TT 2048
#define CC 1024
#define HH 64
#define NROWS (BB * TT)   // 8192

__device__ float g_q[NROWS * HH];
__device__ float g_k[NROWS * HH];
__device__ float g_v[NROWS * HH];

typedef unsigned long long ull;

// ---------------- f32x2 helpers ----------------
__device__ __forceinline__ void ffma2(ull& d, ull a, ull b) {
    asm("fma.rn.f32x2 %0, %1, %2, %0;" : "+l"(d) : "l"(a), "l"(b));
}
__device__ __forceinline__ void fmul2(ull& d, ull a) {
    asm("mul.rn.f32x2 %0, %0, %1;" : "+l"(d) : "l"(a));
}
__device__ __forceinline__ ull pack2(float lo, float hi) {
    ull r; asm("mov.b64 %0, {%1, %2};" : "=l"(r) : "f"(lo), "f"(hi)); return r;
}
__device__ __forceinline__ void unpack2(ull v, float& a, float& b) {
    asm("mov.b64 {%0, %1}, %2;" : "=f"(a), "=f"(b) : "l"(v));
}
__device__ __forceinline__ void lds_2x64(ull& a, ull& b, const void* p) {
    uint32_t sa = (uint32_t)__cvta_generic_to_shared(p);
    asm volatile("ld.shared.v2.u64 {%0, %1}, [%2];" : "=l"(a), "=l"(b) : "r"(sa));
}
__device__ __forceinline__ void cp_async16(void* smem_dst, const void* gptr) {
    uint32_t sa = (uint32_t)__cvta_generic_to_shared(smem_dst);
    asm volatile("cp.async.cg.shared.global [%0], [%1], 16;" :: "r"(sa), "l"(gptr));
}
#define CP_COMMIT() asm volatile("cp.async.commit_group;")
#define CP_WAIT(n)  asm volatile("cp.async.wait_group %0;" :: "n"(n))

// ---------------------------------------------------------------------------
// Kernel 1: QKV projection (best measured ~90us, unchanged).
// ---------------------------------------------------------------------------
__global__ __launch_bounds__(128) void proj_kernel(
    const float* __restrict__ x,
    const float* __restrict__ Wq,
    const float* __restrict__ Wk,
    const float* __restrict__ Wv)
{
    const float* W = (blockIdx.y == 0) ? Wq : (blockIdx.y == 1) ? Wk : Wv;
    float* out     = (blockIdx.y == 0) ? g_q : (blockIdx.y == 1) ? g_k : g_v;

    __shared__ float As[2][32][68];
    __shared__ float Bs[2][32][64];

    const int tid  = threadIdx.x;
    const int tm   = tid >> 4;
    const int tn   = tid & 15;
    const int row0 = blockIdx.x * 64;

    int arow[4], akc[4];
#pragma unroll
    for (int s = 0; s < 4; s++) {
        const int ch = tid + s * 128;
        arow[s] = ch >> 3;
        akc[s]  = ch & 7;
    }
    ull acc[4][4] = {};
    float4 ar[4];

#pragma unroll
    for (int s = 0; s < 4; s++)
        ar[s] = *(const float4*)&x[(row0 + arow[s]) * CC + akc[s] * 4];
#pragma unroll
    for (int s = 0; s < 4; s++) {
        const int ch = tid + s * 128;
        const int k = ch >> 4, nc = ch & 15;
        cp_async16(&Bs[0][k][nc * 4], &W[k * HH + nc * 4]);
    }
    CP_COMMIT();
#pragma unroll
    for (int s = 0; s < 4; s++) {
        As[0][akc[s] * 4 + 0][arow[s]] = ar[s].x;
        As[0][akc[s] * 4 + 1][arow[s]] = ar[s].y;
        As[0][akc[s] * 4 + 2][arow[s]] = ar[s].z;
        As[0][akc[s] * 4 + 3][arow[s]] = ar[s].w;
    }
#pragma unroll
    for (int s = 0; s < 4; s++)
        ar[s] = *(const float4*)&x[(row0 + arow[s]) * CC + 32 + akc[s] * 4];
    CP_WAIT(0);
    __syncthreads();

    for (int t = 0; t < 32; t++) {
        const int buf = t & 1;
        if (t < 31) {
            const int k0n = (t + 1) * 32;
#pragma unroll
            for (int s = 0; s < 4; s++) {
                const int ch = tid + s * 128;
                const int k = ch >> 4, nc = ch & 15;
                cp_async16(&Bs[buf ^ 1][k][nc * 4], &W[(k0n + k) * HH + nc * 4]);
            }
            CP_COMMIT();
#pragma unroll
            for (int s = 0; s < 4; s++) {
                As[buf ^ 1][akc[s] * 4 + 0][arow[s]] = ar[s].x;
                As[buf ^ 1][akc[s] * 4 + 1][arow[s]] = ar[s].y;
                As[buf ^ 1][akc[s] * 4 + 2][arow[s]] = ar[s].z;
                As[buf ^ 1][akc[s] * 4 + 3][arow[s]] = ar[s].w;
            }
        }

#pragma unroll 16
        for (int k = 0; k < 32; k++) {
            ull a01, a23, a45, a67;
            lds_2x64(a01, a23, &As[buf][k][tm * 8]);
            lds_2x64(a45, a67, &As[buf][k][tm * 8 + 4]);
            float4 b4 = *(const float4*)&Bs[buf][k][tn * 4];
            const ull b0 = pack2(b4.x, b4.x);
            const ull b1 = pack2(b4.y, b4.y);
            const ull b2 = pack2(b4.z, b4.z);
            const ull b3 = pack2(b4.w, b4.w);
            ffma2(acc[0][0], a01, b0); ffma2(acc[0][1], a01, b1);
            ffma2(acc[0][2], a01, b2); ffma2(acc[0][3], a01, b3);
            ffma2(acc[1][0], a23, b0); ffma2(acc[1][1], a23, b1);
            ffma2(acc[1][2], a23, b2); ffma2(acc[1][3], a23, b3);
            ffma2(acc[2][0], a45, b0); ffma2(acc[2][1], a45, b1);
            ffma2(acc[2][2], a45, b2); ffma2(acc[2][3], a45, b3);
            ffma2(acc[3][0], a67, b0); ffma2(acc[3][1], a67, b1);
            ffma2(acc[3][2], a67, b2); ffma2(acc[3][3], a67, b3);
        }

        if (t < 31) {
            if (t < 30) {
                const int k0nn = (t + 2) * 32;
#pragma unroll
                for (int s = 0; s < 4; s++)
                    ar[s] = *(const float4*)&x[(row0 + arow[s]) * CC + k0nn + akc[s] * 4];
            }
            CP_WAIT(0);
            __syncthreads();
        }
    }

#pragma unroll
    for (int mp = 0; mp < 4; mp++) {
        float lo0, hi0, lo1, hi1, lo2, hi2, lo3, hi3;
        unpack2(acc[mp][0], lo0, hi0);
        unpack2(acc[mp][1], lo1, hi1);
        unpack2(acc[mp][2], lo2, hi2);
        unpack2(acc[mp][3], lo3, hi3);
        float* r0 = &out[(row0 + tm * 8 + 2 * mp) * HH + tn * 4];
        float* r1 = &out[(row0 + tm * 8 + 2 * mp + 1) * HH + tn * 4];
        *(float4*)r0 = make_float4(lo0, lo1, lo2, lo3);
        *(float4*)r1 = make_float4(hi0, hi1, hi2, hi3);
    }
}

// ---------------------------------------------------------------------------
// Kernel 2: causal attention. 256 blocks (heavy q-tiles first; wave-2 HW
// work-steal balances). 128 threads / 4 warps, 8 rows/warp -> 32-row q-tile.
// 64-key cp.async double-buffered tiles. Lane l: score cols / out dims
// {l, l+32}. P buffered in regs -> 2x STS.128/col; PV via transposed-PT
// 32B broadcasts + coalesced V. smem 80KB -> 2 blocks/SM.
// ---------------------------------------------------------------------------
#define SMA_K(buf)  (sm + (buf) * 4096)            // [64][64] swizzled
#define SMA_V(buf)  (sm + 8192 + (buf) * 4096)     // [64][64] linear
#define SMA_Q       (sm + 16384)                   // [32][64]
#define SMA_PT      (sm + 18432)                   // [4][64][8]
#define ATTN_SMEM_BYTES (20480 * 4)                // 81920 = 80KB

__global__ __launch_bounds__(128) void attn_kernel(float* __restrict__ out)
{
    extern __shared__ float sm[];

    const int bx  = blockIdx.x;
    const int qt  = 63 - (bx >> 2);    // heavy tiles dispatched first
    const int b   = bx & 3;
    const int qs  = qt * 32;
    const int tid = threadIdx.x;
    const int w   = tid >> 5;
    const int l   = tid & 31;

    const float* qb = g_q + b * TT * HH;
    const float* kb = g_k + b * TT * HH;
    const float* vb = g_v + b * TT * HH;
    float*       ob = out + b * TT * HH;

    float* ptw = SMA_PT + (w << 9);    // [64][8]

    const int nkb = (qs + 32 + 63) >> 6;

    // ---- prologue: Q + K0/V0 via cp.async ----
#pragma unroll
    for (int s = 0; s < 4; s++) {
        const int ch = tid + s * 128;             // 0..511
        cp_async16(SMA_Q + ch * 4, &qb[qs * 64 + ch * 4]);
    }
#pragma unroll
    for (int s = 0; s < 8; s++) {
        const int ch = tid + s * 128;             // 0..1023
        const int row = ch >> 4, c4 = ch & 15;
        cp_async16(SMA_K(0) + row * 64 + ((c4 ^ (row & 7)) << 2),
                   &kb[row * 64 + c4 * 4]);
        cp_async16(SMA_V(0) + row * 64 + c4 * 4, &vb[row * 64 + c4 * 4]);
    }
    CP_COMMIT();

    float m[8], lsum[8];
    ull accL[4] = {0ull, 0ull, 0ull, 0ull};   // dim l:    row pairs {0,1}..{6,7}
    ull accH[4] = {0ull, 0ull, 0ull, 0ull};   // dim l+32
#pragma unroll
    for (int i = 0; i < 8; i++) { m[i] = -INFINITY; lsum[i] = 0.f; }

    for (int t = 0; t < nkb; t++) {
        const int buf = t & 1;
        CP_WAIT(0);
        __syncthreads();              // tile t (and Q) ready; prev buf free

        if (t + 1 < nkb) {
            const float* kn = &kb[(t + 1) * 64 * 64];
            const float* vn = &vb[(t + 1) * 64 * 64];
#pragma unroll
            for (int s = 0; s < 8; s++) {
                const int ch = tid + s * 128;
                const int row = ch >> 4, c4 = ch & 15;
                cp_async16(SMA_K(buf ^ 1) + row * 64 + ((c4 ^ (row & 7)) << 2),
                           kn + row * 64 + c4 * 4);
                cp_async16(SMA_V(buf ^ 1) + row * 64 + c4 * 4,
                           vn + row * 64 + c4 * 4);
            }
            CP_COMMIT();
        }

        const float* Ks = SMA_K(buf);
        const float* Vb = SMA_V(buf);

        // ---- scores: 8 rows/warp, k-packed f32x2 ----
        ull s2[8][2] = {};
#pragma unroll
        for (int c4 = 0; c4 < 16; c4++) {
            ull kl0, kl1, kh0, kh1;
            lds_2x64(kl0, kl1, &Ks[l * 64 + ((c4 ^ (l & 7)) << 2)]);
            lds_2x64(kh0, kh1, &Ks[(l + 32) * 64 + ((c4 ^ (l & 7)) << 2)]);
#pragma unroll
            for (int i = 0; i < 8; i++) {
                ull q0, q1;
                lds_2x64(q0, q1, &SMA_Q[((w << 3) + i) * 64 + c4 * 4]);
                ffma2(s2[i][0], q0, kl0); ffma2(s2[i][0], q1, kl1);
                ffma2(s2[i][1], q0, kh0); ffma2(s2[i][1], q1, kh1);
            }
        }

        // ---- online softmax (exact reference mask), P kept in regs ----
        const int col0 = t * 64 + l;
        const int col1 = col0 + 32;
        float f[8], p0r[8], p1r[8];
#pragma unroll
        for (int i = 0; i < 8; i++) {
            const int rowg = qs + (w << 3) + i;
            float lo, hi, sc0, sc1;
            unpack2(s2[i][0], lo, hi);  sc0 = (lo + hi) * 0.125f;
            unpack2(s2[i][1], lo, hi);  sc1 = (lo + hi) * 0.125f;
            if (col0 > rowg || sc0 == 0.0f) sc0 = -INFINITY;
            if (col1 > rowg || sc1 == 0.0f) sc1 = -INFINITY;

            float rmax = fmaxf(sc0, sc1);
#pragma unroll
            for (int off = 16; off > 0; off >>= 1)
                rmax = fmaxf(rmax, __shfl_xor_sync(0xffffffffu, rmax, off));

            const float mnew = fmaxf(m[i], rmax);
            f[i]   = __expf(m[i] - mnew);
            p0r[i] = __expf(sc0 - mnew);
            p1r[i] = __expf(sc1 - mnew);

            float psum = p0r[i] + p1r[i];
#pragma unroll
            for (int off = 16; off > 0; off >>= 1)
                psum += __shfl_xor_sync(0xffffffffu, psum, off);

            lsum[i] = lsum[i] * f[i] + psum;
            m[i] = mnew;
        }
        // rescale accumulators (row-pair packed factors)
#pragma unroll
        for (int rp = 0; rp < 4; rp++) {
            const ull f2 = pack2(f[2 * rp], f[2 * rp + 1]);
            fmul2(accL[rp], f2);
            fmul2(accH[rp], f2);
        }
        // vector stores of P into transposed PT[key][8]
        *(float4*)&ptw[l * 8]            = make_float4(p0r[0], p0r[1], p0r[2], p0r[3]);
        *(float4*)&ptw[l * 8 + 4]        = make_float4(p0r[4], p0r[5], p0r[6], p0r[7]);
        *(float4*)&ptw[(l + 32) * 8]     = make_float4(p1r[0], p1r[1], p1r[2], p1r[3]);
        *(float4*)&ptw[(l + 32) * 8 + 4] = make_float4(p1r[4], p1r[5], p1r[6], p1r[7]);
        __syncwarp();

        // ---- P @ V : row-pair packed; P = 32B broadcast, V coalesced ----
#pragma unroll 4
        for (int j = 0; j < 64; j++) {
            ull p01, p23, p45, p67;
            lds_2x64(p01, p23, &ptw[j * 8]);
            lds_2x64(p45, p67, &ptw[j * 8 + 4]);
            const float v0 = Vb[j * 64 + l];
            const float v1 = Vb[j * 64 + l + 32];
            const ull vv0 = pack2(v0, v0);
            const ull vv1 = pack2(v1, v1);
            ffma2(accL[0], p01, vv0); ffma2(accL[1], p23, vv0);
            ffma2(accL[2], p45, vv0); ffma2(accL[3], p67, vv0);
            ffma2(accH[0], p01, vv1); ffma2(accH[1], p23, vv1);
            ffma2(accH[2], p45, vv1); ffma2(accH[3], p67, vv1);
        }
        __syncthreads();              // all warps done with buf before refill
    }

    // ---- epilogue ----
#pragma unroll
    for (int rp = 0; rp < 4; rp++) {
        const float inv0 = 1.0f / lsum[2 * rp];
        const float inv1 = 1.0f / lsum[2 * rp + 1];
        float a0, a1;
        unpack2(accL[rp], a0, a1);
        ob[(qs + (w << 3) + 2 * rp) * HH + l]     = a0 * inv0;
        ob[(qs + (w << 3) + 2 * rp + 1) * HH + l] = a1 * inv1;
        unpack2(accH[rp], a0, a1);
        ob[(qs + (w << 3) + 2 * rp) * HH + l + 32]     = a0 * inv0;
        ob[(qs + (w << 3) + 2 * rp + 1) * HH + l + 32] = a1 * inv1;
    }
}

// ---------------------------------------------------------------------------
extern "C" void kernel_launch(void* const* d_in, const int* in_sizes, int n_in,
                              void* d_out, int out_size)
{
    const float* x  = (const float*)d_in[0];
    const float* Wq = (const float*)d_in[1];
    const float* Wk = (const float*)d_in[2];
    const float* Wv = (const float*)d_in[3];
    float* out = (float*)d_out;

    static int smem_set = 0;
    if (!smem_set) {
        cudaFuncSetAttribute(attn_kernel,
                             cudaFuncAttributeMaxDynamicSharedMemorySize,
                             ATTN_SMEM_BYTES);
        smem_set = 1;
    }

    proj_kernel<<<dim3(NROWS / 64, 3), 128>>>(x, Wq, Wk, Wv);
    attn_kernel<<<256, 128, ATTN_SMEM_BYTES>>>(out);
}

// round 11
// speedup vs baseline: 1.3522x; 1.3522x over previous
#include <cuda_runtime.h>
#include <cuda_bf16.h>
#include <math.h>
#include <stdint.h>

#define BB 4
#define TT 2048
#define CC 1024
#define HH 64
#define NROWS (BB * TT)   // 8192

__device__ float g_q[NROWS * HH];
__device__ float g_k[NROWS * HH];
__device__ float g_v[NROWS * HH];
// A fragments: [mtile(512)][kstep(64)][prec(2)][lane(32)][reg(4)] u32
__device__ uint32_t g_afrag[512 * 64 * 2 * 128];
// B fragments: [kstep(64)][ntile(24)][prec(2)][lane(32)][reg(2)] u32
__device__ uint32_t g_bfrag[64 * 24 * 2 * 64];

typedef unsigned long long ull;

// ---------------- f32x2 helpers (attn) ----------------
__device__ __forceinline__ void ffma2(ull& d, ull a, ull b) {
    asm("fma.rn.f32x2 %0, %1, %2, %0;" : "+l"(d) : "l"(a), "l"(b));
}
__device__ __forceinline__ void fmul2(ull& d, ull a) {
    asm("mul.rn.f32x2 %0, %0, %1;" : "+l"(d) : "l"(a));
}
__device__ __forceinline__ ull pack2(float lo, float hi) {
    ull r; asm("mov.b64 %0, {%1, %2};" : "=l"(r) : "f"(lo), "f"(hi)); return r;
}
__device__ __forceinline__ void unpack2(ull v, float& a, float& b) {
    asm("mov.b64 {%0, %1}, %2;" : "=f"(a), "=f"(b) : "l"(v));
}
__device__ __forceinline__ void lds_2x64(ull& a, ull& b, const void* p) {
    uint32_t sa = (uint32_t)__cvta_generic_to_shared(p);
    asm volatile("ld.shared.v2.u64 {%0, %1}, [%2];" : "=l"(a), "=l"(b) : "r"(sa));
}
__device__ __forceinline__ void cp_async16(void* smem_dst, const void* gptr) {
    uint32_t sa = (uint32_t)__cvta_generic_to_shared(smem_dst);
    asm volatile("cp.async.cg.shared.global [%0], [%1], 16;" :: "r"(sa), "l"(gptr));
}
#define CP_COMMIT() asm volatile("cp.async.commit_group;")
#define CP_WAIT(n)  asm volatile("cp.async.wait_group %0;" :: "n"(n))

// ---------------- bf16 + mma helpers ----------------
__device__ __forceinline__ uint32_t pack_bf16x2(float a, float b) {
    __nv_bfloat162 t;
    t.x = __float2bfloat16_rn(a);
    t.y = __float2bfloat16_rn(b);
    return *(uint32_t*)&t;
}
__device__ __forceinline__ void split2(float a, float b, uint32_t& hi, uint32_t& lo) {
    __nv_bfloat16 ha = __float2bfloat16_rn(a);
    __nv_bfloat16 hb = __float2bfloat16_rn(b);
    __nv_bfloat162 th; th.x = ha; th.y = hb;
    hi = *(uint32_t*)&th;
    lo = pack_bf16x2(a - __bfloat162float(ha), b - __bfloat162float(hb));
}
__device__ __forceinline__ void mma_bf16(float* c, const uint32_t* a, const uint32_t* b) {
    asm volatile(
        "mma.sync.aligned.m16n8k16.row.col.f32.bf16.bf16.f32 "
        "{%0,%1,%2,%3}, {%4,%5,%6,%7}, {%8,%9}, {%0,%1,%2,%3};"
        : "+f"(c[0]), "+f"(c[1]), "+f"(c[2]), "+f"(c[3])
        : "r"(a[0]), "r"(a[1]), "r"(a[2]), "r"(a[3]), "r"(b[0]), "r"(b[1]));
}

// ---------------------------------------------------------------------------
// Kernel 0a: x -> bf16 (hi,lo) A-fragments, HMMA register order.
// Thread = (mtile, kstep, lane); reg r: m = mt*16 + (l>>2) + (r&1)*8,
// k = ks*16 + (l&3)*2 + (r>>1)*8, two consecutive k packed per u32.
// grid 4096 x 256 (8 warps = 8 (mt,ks) units per block).
// ---------------------------------------------------------------------------
__global__ __launch_bounds__(256) void split_a_kernel(const float* __restrict__ x)
{
    const int unit = blockIdx.x * 8 + (threadIdx.x >> 5);
    const int lane = threadIdx.x & 31;
    const int mt   = unit >> 6;
    const int ks   = unit & 63;
    const uint32_t base = (uint32_t)(mt * 64 + ks) * 256;

#pragma unroll
    for (int r = 0; r < 4; r++) {
        const int m = mt * 16 + (lane >> 2) + ((r & 1) << 3);
        const int k = ks * 16 + ((lane & 3) << 1) + ((r >> 1) << 3);
        const float2 v = *(const float2*)&x[(size_t)m * CC + k];
        uint32_t hi, lo;
        split2(v.x, v.y, hi, lo);
        g_afrag[base + lane * 4 + r]       = hi;
        g_afrag[base + 128 + lane * 4 + r] = lo;
    }
}

// ---------------------------------------------------------------------------
// Kernel 0b: W -> bf16 (hi,lo) B-fragments (col-major B for row.col mma).
// Thread = (kstep, ntile, lane); reg r: k = ks*16 + (l&3)*2 + r*8 (+j),
// n = nt*8 + (l>>2). n global 0..191 selects Wq/Wk/Wv.
// grid 192 x 256.
// ---------------------------------------------------------------------------
__global__ __launch_bounds__(256) void split_b_kernel(
    const float* __restrict__ Wq,
    const float* __restrict__ Wk,
    const float* __restrict__ Wv)
{
    const int idx  = blockIdx.x * 256 + threadIdx.x;
    const int lane = idx & 31;
    const int nt   = (idx >> 5) % 24;
    const int ks   = idx / 768;
    const int n    = nt * 8 + (lane >> 2);
    const float* W = (n < 64) ? Wq : (n < 128) ? Wk : Wv;
    const int nc   = n & 63;
    const uint32_t base = (uint32_t)(ks * 24 + nt) * 128;

#pragma unroll
    for (int r = 0; r < 2; r++) {
        const int k = ks * 16 + ((lane & 3) << 1) + (r << 3);
        const float v0 = W[k * HH + nc];
        const float v1 = W[(k + 1) * HH + nc];
        uint32_t hi, lo;
        split2(v0, v1, hi, lo);
        g_bfrag[base + lane * 2 + r]      = hi;
        g_bfrag[base + 64 + lane * 2 + r] = lo;
    }
}

// ---------------------------------------------------------------------------
// Kernel 1: QKV projection via mma.sync bf16 split precision.
// 128 CTAs x 128 threads (4 warps). CTA: 64 rows x N=192. Warp w: m-tile w.
// K = 64 steps of 16; per step per warp: 24 n-tiles x 3 products = 72 HMMA.
// Fragments come fragment-packed from global; smem loads are contiguous.
// ---------------------------------------------------------------------------
__global__ __launch_bounds__(128) void gemm_kernel()
{
    __shared__ uint32_t As[2][4 * 256];    // 8 KB: [mt][prec(128)+...]
    __shared__ uint32_t Bs[2][24 * 128];   // 24 KB: [nt][prec(64)+...]

    const int tid  = threadIdx.x;
    const int w    = tid >> 5;
    const int lane = tid & 31;
    const int mt0  = blockIdx.x * 4;
    const int row0 = blockIdx.x * 64;

    float acc[24][4];
#pragma unroll
    for (int nt = 0; nt < 24; nt++)
#pragma unroll
        for (int e = 0; e < 4; e++) acc[nt][e] = 0.f;

    // prologue: kstep 0 -> buf 0
    {
#pragma unroll
        for (int i = 0; i < 2; i++) {
            const int u = tid + i * 128;             // 0..255 (16B units)
            const int chunk = u >> 6;
            const int within = (u & 63) * 4;
            cp_async16(&As[0][chunk * 256 + within],
                       g_afrag + (uint32_t)((mt0 + chunk) * 64 + 0) * 256 + within);
        }
#pragma unroll
        for (int i = 0; i < 6; i++) {
            const int u = tid + i * 128;             // 0..767
            cp_async16(&Bs[0][u * 4], g_bfrag + u * 4);
        }
        CP_COMMIT();
    }

    for (int ks = 0; ks < 64; ks++) {
        const int buf = ks & 1;
        CP_WAIT(0);
        __syncthreads();          // tile ks resident; all warps past ks-1 compute

        if (ks + 1 < 64) {
#pragma unroll
            for (int i = 0; i < 2; i++) {
                const int u = tid + i * 128;
                const int chunk = u >> 6;
                const int within = (u & 63) * 4;
                cp_async16(&As[buf ^ 1][chunk * 256 + within],
                           g_afrag + (uint32_t)((mt0 + chunk) * 64 + ks + 1) * 256 + within);
            }
#pragma unroll
            for (int i = 0; i < 6; i++) {
                const int u = tid + i * 128;
                cp_async16(&Bs[buf ^ 1][u * 4],
                           g_bfrag + (uint32_t)(ks + 1) * 3072 + u * 4);
            }
            CP_COMMIT();
        }

        // A fragments for this warp's m-tile (contiguous per lane)
        uint32_t ah[4], al[4];
        *(uint4*)ah = *(const uint4*)&As[buf][w * 256 + lane * 4];
        *(uint4*)al = *(const uint4*)&As[buf][w * 256 + 128 + lane * 4];

#pragma unroll
        for (int nt = 0; nt < 24; nt++) {
            uint32_t bh[2], bl[2];
            *(uint2*)bh = *(const uint2*)&Bs[buf][nt * 128 + lane * 2];
            *(uint2*)bl = *(const uint2*)&Bs[buf][nt * 128 + 64 + lane * 2];
            mma_bf16(acc[nt], ah, bh);
            mma_bf16(acc[nt], ah, bl);
            mma_bf16(acc[nt], al, bh);
        }
    }

    // epilogue
    const int row = row0 + w * 16 + (lane >> 2);
#pragma unroll
    for (int nt = 0; nt < 24; nt++) {
        float* dst = (nt < 8) ? g_q : (nt < 16) ? g_k : g_v;
        const int c0 = (nt & 7) * 8 + ((lane & 3) << 1);
        *(float2*)&dst[(size_t)row * HH + c0]       = make_float2(acc[nt][0], acc[nt][1]);
        *(float2*)&dst[(size_t)(row + 8) * HH + c0] = make_float2(acc[nt][2], acc[nt][3]);
    }
}

// ---------------------------------------------------------------------------
// Kernel 2: causal attention — best measured variant (91.5us, round 3).
// 256 threads / 8 warps, phases (p, 63-p) of 32 rows, 128-key cp.async
// double-buffered tiles, f32x2, exact reference mask semantics.
// ---------------------------------------------------------------------------
#define SM_K(buf)  (sm + (buf) * 8192)
#define SM_V(buf)  (sm + 16384 + (buf) * 8192)
#define SM_Q       (sm + 32768)
#define SM_PT      (sm + 34816)
#define ATTN_SMEM_BYTES ((34816 + 4096) * 4)      // 155648 = 152KB

__global__ __launch_bounds__(256, 1) void attn_kernel(float* __restrict__ out)
{
    extern __shared__ float sm[];

    const int b   = blockIdx.y;
    const int p   = blockIdx.x;
    const int tid = threadIdx.x;
    const int w   = tid >> 5;
    const int l   = tid & 31;

    const float* qb = g_q + b * TT * HH;
    const float* kb = g_k + b * TT * HH;
    const float* vb = g_v + b * TT * HH;
    float*       ob = out + b * TT * HH;

    float* ptw = SM_PT + (w << 9);   // [128][4]

    for (int phase = 0; phase < 2; phase++) {
        const int qt = phase ? (63 - p) : p;
        const int qs = qt * 32;

        __syncthreads();

        for (int idx = tid; idx < 32 * 64; idx += 256)
            SM_Q[idx] = qb[qs * 64 + idx];

        float m[4], lsum[4];
        ull acc01[2] = {0ull, 0ull};
        ull acc23[2] = {0ull, 0ull};
#pragma unroll
        for (int i = 0; i < 4; i++) { m[i] = -INFINITY; lsum[i] = 0.f; }

        const int nkb = (qs + 32 + 127) >> 7;

        {
#pragma unroll
            for (int s = 0; s < 8; s++) {
                const int chunk = s * 256 + tid;
                const int row = chunk >> 4, c4 = chunk & 15;
                cp_async16(SM_K(0) + row * 64 + ((c4 ^ (row & 7)) << 2),
                           &kb[row * 64 + c4 * 4]);
            }
#pragma unroll
            for (int s = 0; s < 8; s++) {
                const int chunk = s * 256 + tid;
                const int row = chunk >> 4, c4 = chunk & 15;
                cp_async16(SM_V(0) + row * 64 + c4 * 4,
                           &vb[row * 64 + c4 * 4]);
            }
            CP_COMMIT();
        }

        for (int t = 0; t < nkb; t++) {
            const int buf = t & 1;
            if (t + 1 < nkb) {
                const float* kt_ = &kb[(t + 1) * 128 * 64];
                const float* vt_ = &vb[(t + 1) * 128 * 64];
#pragma unroll
                for (int s = 0; s < 8; s++) {
                    const int chunk = s * 256 + tid;
                    const int row = chunk >> 4, c4 = chunk & 15;
                    cp_async16(SM_K(buf ^ 1) + row * 64 + ((c4 ^ (row & 7)) << 2),
                               kt_ + row * 64 + c4 * 4);
                }
#pragma unroll
                for (int s = 0; s < 8; s++) {
                    const int chunk = s * 256 + tid;
                    const int row = chunk >> 4, c4 = chunk & 15;
                    cp_async16(SM_V(buf ^ 1) + row * 64 + c4 * 4,
                               vt_ + row * 64 + c4 * 4);
                }
                CP_COMMIT();
                CP_WAIT(1);
            } else {
                CP_WAIT(0);
            }
            __syncthreads();

            const float* Ks = SM_K(buf);
            const float* Vb = SM_V(buf);

            ull s2[4][4] = {};
#pragma unroll
            for (int c4 = 0; c4 < 16; c4++) {
                ull k2[4][2];
#pragma unroll
                for (int cc = 0; cc < 4; cc++)
                    lds_2x64(k2[cc][0], k2[cc][1],
                             &Ks[(l + 32 * cc) * 64 + ((c4 ^ (l & 7)) << 2)]);
                ull q2[2];
#pragma unroll
                for (int i = 0; i < 4; i++) {
                    lds_2x64(q2[0], q2[1], &SM_Q[((w << 2) + i) * 64 + c4 * 4]);
#pragma unroll
                    for (int cc = 0; cc < 4; cc++) {
                        ffma2(s2[i][cc], q2[0], k2[cc][0]);
                        ffma2(s2[i][cc], q2[1], k2[cc][1]);
                    }
                }
            }

            float f[4];
#pragma unroll
            for (int i = 0; i < 4; i++) {
                const int rowg = qs + (w << 2) + i;
                float sc[4];
#pragma unroll
                for (int cc = 0; cc < 4; cc++) {
                    float lo, hi; unpack2(s2[i][cc], lo, hi);
                    float s = (lo + hi) * 0.125f;
                    const int col = t * 128 + l + 32 * cc;
                    if (col > rowg || s == 0.0f) s = -INFINITY;
                    sc[cc] = s;
                }
                float rmax = fmaxf(fmaxf(sc[0], sc[1]), fmaxf(sc[2], sc[3]));
#pragma unroll
                for (int off = 16; off > 0; off >>= 1)
                    rmax = fmaxf(rmax, __shfl_xor_sync(0xffffffffu, rmax, off));

                const float mnew = fmaxf(m[i], rmax);
                f[i] = __expf(m[i] - mnew);
                float pv[4], psum = 0.f;
#pragma unroll
                for (int cc = 0; cc < 4; cc++) { pv[cc] = __expf(sc[cc] - mnew); psum += pv[cc]; }
#pragma unroll
                for (int off = 16; off > 0; off >>= 1)
                    psum += __shfl_xor_sync(0xffffffffu, psum, off);

                lsum[i] = lsum[i] * f[i] + psum;
                m[i] = mnew;
#pragma unroll
                for (int cc = 0; cc < 4; cc++)
                    ptw[(l + 32 * cc) * 4 + i] = pv[cc];
            }
            {
                ull f01 = pack2(f[0], f[1]);
                ull f23 = pack2(f[2], f[3]);
                fmul2(acc01[0], f01); fmul2(acc01[1], f01);
                fmul2(acc23[0], f23); fmul2(acc23[1], f23);
            }
            __syncwarp();

#pragma unroll 4
            for (int j = 0; j < 128; j++) {
                ull p01, p23;
                lds_2x64(p01, p23, &ptw[j * 4]);
                const float v0 = Vb[j * 64 + l];
                const float v1 = Vb[j * 64 + l + 32];
                const ull vv0 = pack2(v0, v0);
                const ull vv1 = pack2(v1, v1);
                ffma2(acc01[0], p01, vv0);
                ffma2(acc23[0], p23, vv0);
                ffma2(acc01[1], p01, vv1);
                ffma2(acc23[1], p23, vv1);
            }
            __syncthreads();
        }

        float o01a, o01b, o23a, o23b;
        float inv0 = 1.0f / lsum[0], inv1 = 1.0f / lsum[1];
        float inv2 = 1.0f / lsum[2], inv3 = 1.0f / lsum[3];
        unpack2(acc01[0], o01a, o01b);
        unpack2(acc23[0], o23a, o23b);
        ob[(qs + (w << 2) + 0) * HH + l] = o01a * inv0;
        ob[(qs + (w << 2) + 1) * HH + l] = o01b * inv1;
        ob[(qs + (w << 2) + 2) * HH + l] = o23a * inv2;
        ob[(qs + (w << 2) + 3) * HH + l] = o23b * inv3;
        unpack2(acc01[1], o01a, o01b);
        unpack2(acc23[1], o23a, o23b);
        ob[(qs + (w << 2) + 0) * HH + l + 32] = o01a * inv0;
        ob[(qs + (w << 2) + 1) * HH + l + 32] = o01b * inv1;
        ob[(qs + (w << 2) + 2) * HH + l + 32] = o23a * inv2;
        ob[(qs + (w << 2) + 3) * HH + l + 32] = o23b * inv3;
    }
}

// ---------------------------------------------------------------------------
extern "C" void kernel_launch(void* const* d_in, const int* in_sizes, int n_in,
                              void* d_out, int out_size)
{
    const float* x  = (const float*)d_in[0];
    const float* Wq = (const float*)d_in[1];
    const float* Wk = (const float*)d_in[2];
    const float* Wv = (const float*)d_in[3];
    float* out = (float*)d_out;

    static int smem_set = 0;
    if (!smem_set) {
        cudaFuncSetAttribute(attn_kernel,
                             cudaFuncAttributeMaxDynamicSharedMemorySize,
                             ATTN_SMEM_BYTES);
        smem_set = 1;
    }

    split_a_kernel<<<4096, 256>>>(x);
    split_b_kernel<<<192, 256>>>(Wq, Wk, Wv);
    gemm_kernel<<<128, 128>>>();
    attn_kernel<<<dim3(32, BB), 256, ATTN_SMEM_BYTES>>>(out);
}

// round 12
// speedup vs baseline: 1.8747x; 1.3864x over previous
#include <cuda_runtime.h>
#include <cuda_bf16.h>
#include <math.h>
#include <stdint.h>

#define BB 4
#define TT 2048
#define CC 1024
#define HH 64
#define NROWS (BB * TT)   // 8192

// x fragments for proj GEMM (unchanged from R11)
__device__ uint32_t g_afrag[512 * 64 * 2 * 128];
__device__ uint32_t g_bfrag[64 * 24 * 2 * 64];
// q/k/v in mma fragment form, produced by gemm epilogue
__device__ uint32_t g_qf[4 * 128 * 4 * 2 * 128];   // [b][mtile][ks][prec][lane*4+r]
__device__ uint32_t g_kf[4 * 256 * 4 * 2 * 64];    // [b][keyblk][ks][prec][lane*2+r]
__device__ uint32_t g_vf[4 * 128 * 8 * 2 * 64];    // [b][keytile][nt][prec][lane*2+r]

typedef unsigned long long ull;
union U64 { ull u; uint32_t s[2]; };

// ---------------- helpers ----------------
__device__ __forceinline__ ull lds_u64(const void* p) {
    uint32_t sa = (uint32_t)__cvta_generic_to_shared(p);
    ull r;
    asm volatile("ld.shared.u64 %0, [%1];" : "=l"(r) : "r"(sa));
    return r;
}
__device__ __forceinline__ void cp_async16(void* smem_dst, const void* gptr) {
    uint32_t sa = (uint32_t)__cvta_generic_to_shared(smem_dst);
    asm volatile("cp.async.cg.shared.global [%0], [%1], 16;" :: "r"(sa), "l"(gptr));
}
#define CP_COMMIT() asm volatile("cp.async.commit_group;")
#define CP_WAIT(n)  asm volatile("cp.async.wait_group %0;" :: "n"(n))

__device__ __forceinline__ uint32_t pack_bf16x2(float a, float b) {
    __nv_bfloat162 t;
    t.x = __float2bfloat16_rn(a);
    t.y = __float2bfloat16_rn(b);
    return *(uint32_t*)&t;
}
__device__ __forceinline__ void split2(float a, float b, uint32_t& hi, uint32_t& lo) {
    __nv_bfloat16 ha = __float2bfloat16_rn(a);
    __nv_bfloat16 hb = __float2bfloat16_rn(b);
    __nv_bfloat162 th; th.x = ha; th.y = hb;
    hi = *(uint32_t*)&th;
    lo = pack_bf16x2(a - __bfloat162float(ha), b - __bfloat162float(hb));
}
__device__ __forceinline__ void mma_bf16(float* c, const uint32_t* a, const uint32_t* b) {
    asm volatile(
        "mma.sync.aligned.m16n8k16.row.col.f32.bf16.bf16.f32 "
        "{%0,%1,%2,%3}, {%4,%5,%6,%7}, {%8,%9}, {%0,%1,%2,%3};"
        : "+f"(c[0]), "+f"(c[1]), "+f"(c[2]), "+f"(c[3])
        : "r"(a[0]), "r"(a[1]), "r"(a[2]), "r"(a[3]), "r"(b[0]), "r"(b[1]));
}

// ---------------------------------------------------------------------------
// Kernel 0a: x -> bf16 (hi,lo) A-fragments (unchanged from R11).
// ---------------------------------------------------------------------------
__global__ __launch_bounds__(256) void split_a_kernel(const float* __restrict__ x)
{
    const int unit = blockIdx.x * 8 + (threadIdx.x >> 5);
    const int lane = threadIdx.x & 31;
    const int mt   = unit >> 6;
    const int ks   = unit & 63;
    const uint32_t base = (uint32_t)(mt * 64 + ks) * 256;

#pragma unroll
    for (int r = 0; r < 4; r++) {
        const int m = mt * 16 + (lane >> 2) + ((r & 1) << 3);
        const int k = ks * 16 + ((lane & 3) << 1) + ((r >> 1) << 3);
        const float2 v = *(const float2*)&x[(size_t)m * CC + k];
        uint32_t hi, lo;
        split2(v.x, v.y, hi, lo);
        g_afrag[base + lane * 4 + r]       = hi;
        g_afrag[base + 128 + lane * 4 + r] = lo;
    }
}

// ---------------------------------------------------------------------------
// Kernel 0b: W -> bf16 (hi,lo) B-fragments (unchanged from R11).
// ---------------------------------------------------------------------------
__global__ __launch_bounds__(256) void split_b_kernel(
    const float* __restrict__ Wq,
    const float* __restrict__ Wk,
    const float* __restrict__ Wv)
{
    const int idx  = blockIdx.x * 256 + threadIdx.x;
    const int lane = idx & 31;
    const int nt   = (idx >> 5) % 24;
    const int ks   = idx / 768;
    const int n    = nt * 8 + (lane >> 2);
    const float* W = (n < 64) ? Wq : (n < 128) ? Wk : Wv;
    const int nc   = n & 63;
    const uint32_t base = (uint32_t)(ks * 24 + nt) * 128;

#pragma unroll
    for (int r = 0; r < 2; r++) {
        const int k = ks * 16 + ((lane & 3) << 1) + (r << 3);
        const float v0 = W[k * HH + nc];
        const float v1 = W[(k + 1) * HH + nc];
        uint32_t hi, lo;
        split2(v0, v1, hi, lo);
        g_bfrag[base + lane * 2 + r]      = hi;
        g_bfrag[base + 64 + lane * 2 + r] = lo;
    }
}

// ---------------------------------------------------------------------------
// Kernel 1: QKV projection via mma.sync; epilogue emits fragment-form q/k/v.
// 128 CTAs x 128 threads (4 warps). CTA: 64 rows x N=192 (q|k|v).
// ---------------------------------------------------------------------------
__global__ __launch_bounds__(128) void gemm_kernel()
{
    __shared__ uint32_t As[2][4 * 256];    // 8 KB
    __shared__ uint32_t Bs[2][24 * 128];   // 24 KB
    __shared__ float    Vsm[4][16][64];    // 16 KB (total static = 48 KB)

    const int tid  = threadIdx.x;
    const int w    = tid >> 5;
    const int lane = tid & 31;
    const int mt0  = blockIdx.x * 4;
    const int row0 = blockIdx.x * 64;

    float acc[24][4];
#pragma unroll
    for (int nt = 0; nt < 24; nt++)
#pragma unroll
        for (int e = 0; e < 4; e++) acc[nt][e] = 0.f;

    // prologue: kstep 0 -> buf 0
    {
#pragma unroll
        for (int i = 0; i < 2; i++) {
            const int u = tid + i * 128;
            const int chunk = u >> 6;
            const int within = (u & 63) * 4;
            cp_async16(&As[0][chunk * 256 + within],
                       g_afrag + (uint32_t)((mt0 + chunk) * 64 + 0) * 256 + within);
        }
#pragma unroll
        for (int i = 0; i < 6; i++) {
            const int u = tid + i * 128;
            cp_async16(&Bs[0][u * 4], g_bfrag + u * 4);
        }
        CP_COMMIT();
    }

    for (int ks = 0; ks < 64; ks++) {
        const int buf = ks & 1;
        CP_WAIT(0);
        __syncthreads();

        if (ks + 1 < 64) {
#pragma unroll
            for (int i = 0; i < 2; i++) {
                const int u = tid + i * 128;
                const int chunk = u >> 6;
                const int within = (u & 63) * 4;
                cp_async16(&As[buf ^ 1][chunk * 256 + within],
                           g_afrag + (uint32_t)((mt0 + chunk) * 64 + ks + 1) * 256 + within);
            }
#pragma unroll
            for (int i = 0; i < 6; i++) {
                const int u = tid + i * 128;
                cp_async16(&Bs[buf ^ 1][u * 4],
                           g_bfrag + (uint32_t)(ks + 1) * 3072 + u * 4);
            }
            CP_COMMIT();
        }

        uint32_t ah[4], al[4];
        *(uint4*)ah = *(const uint4*)&As[buf][w * 256 + lane * 4];
        *(uint4*)al = *(const uint4*)&As[buf][w * 256 + 128 + lane * 4];

#pragma unroll
        for (int nt = 0; nt < 24; nt++) {
            uint32_t bh[2], bl[2];
            *(uint2*)bh = *(const uint2*)&Bs[buf][nt * 128 + lane * 2];
            *(uint2*)bl = *(const uint2*)&Bs[buf][nt * 128 + 64 + lane * 2];
            mma_bf16(acc[nt], ah, bh);
            mma_bf16(acc[nt], ah, bl);
            mma_bf16(acc[nt], al, bh);
        }
    }

    // ---- epilogue: write fragment-form q/k/v ----
    const int rw  = row0 + w * 16;           // global first row of warp's m-tile
    const int bb  = rw >> 11;                // batch
    const int mtb = (rw & 2047) >> 4;        // m-tile within batch
    const int kb0 = (rw & 2047) >> 3;        // first key-block (of 8 keys)
    const int ktb = mtb;                     // key-tile (16 keys) for V
    const int qlr = lane >> 2;
    const int qlc = lane & 3;

    // Q: A-fragments (dims = k). a0,a1 from dim-tile 2ks; a2,a3 from 2ks+1.
#pragma unroll
    for (int ks = 0; ks < 4; ks++) {
        uint32_t h0, l0, h1, l1, h2, l2, h3, l3;
        split2(acc[2 * ks][0],     acc[2 * ks][1],     h0, l0);
        split2(acc[2 * ks][2],     acc[2 * ks][3],     h1, l1);
        split2(acc[2 * ks + 1][0], acc[2 * ks + 1][1], h2, l2);
        split2(acc[2 * ks + 1][2], acc[2 * ks + 1][3], h3, l3);
        const uint32_t base = (uint32_t)(((bb * 128 + mtb) * 4 + ks) * 2) * 128 + lane * 4;
        *(uint4*)&g_qf[base]       = make_uint4(h0, h1, h2, h3);
        *(uint4*)&g_qf[base + 128] = make_uint4(l0, l1, l2, l3);
    }

    // K: B-fragments (n = keys, k = dims). even key-block from c0c1, odd from c2c3.
#pragma unroll
    for (int ks = 0; ks < 4; ks++) {
        uint32_t b0h, b0l, b1h, b1l;
        // even block (keys rows r)
        split2(acc[8 + 2 * ks][0], acc[8 + 2 * ks][1], b0h, b0l);
        split2(acc[9 + 2 * ks][0], acc[9 + 2 * ks][1], b1h, b1l);
        uint32_t base = (uint32_t)(((bb * 256 + kb0) * 4 + ks) * 2) * 64 + lane * 2;
        *(uint2*)&g_kf[base]      = make_uint2(b0h, b1h);
        *(uint2*)&g_kf[base + 64] = make_uint2(b0l, b1l);
        // odd block (keys rows r+8)
        split2(acc[8 + 2 * ks][2], acc[8 + 2 * ks][3], b0h, b0l);
        split2(acc[9 + 2 * ks][2], acc[9 + 2 * ks][3], b1h, b1l);
        base = (uint32_t)(((bb * 256 + kb0 + 1) * 4 + ks) * 2) * 64 + lane * 2;
        *(uint2*)&g_kf[base]      = make_uint2(b0h, b1h);
        *(uint2*)&g_kf[base + 64] = make_uint2(b0l, b1l);
    }

    // V: stage f32 to smem, then emit transposed B-fragments (n = dims, k = keys).
#pragma unroll
    for (int dt = 0; dt < 8; dt++) {
        const int d0 = dt * 8 + qlc * 2;
        Vsm[w][qlr][d0]         = acc[16 + dt][0];
        Vsm[w][qlr][d0 + 1]     = acc[16 + dt][1];
        Vsm[w][qlr + 8][d0]     = acc[16 + dt][2];
        Vsm[w][qlr + 8][d0 + 1] = acc[16 + dt][3];
    }
    __syncwarp();
#pragma unroll
    for (int nt = 0; nt < 8; nt++) {
#pragma unroll
        for (int r = 0; r < 2; r++) {
            const int kl_ = qlc * 2 + r * 8;
            const int dd  = nt * 8 + qlr;
            uint32_t h, lo;
            split2(Vsm[w][kl_][dd], Vsm[w][kl_ + 1][dd], h, lo);
            const uint32_t base = (uint32_t)(((bb * 128 + ktb) * 8 + nt) * 2) * 64 + lane * 2 + r;
            g_vf[base]      = h;
            g_vf[base + 64] = lo;
        }
    }
}

// ---------------------------------------------------------------------------
// Kernel 2: causal attention, all-HMMA.
// 128 blocks (32 pairs x 4 batches) x 64 threads (2 warps). Phases qt = p,
// 63-p; 32-row q-tiles; warp w = m16 tile. Key tiles of 64 keys, cp.async
// double-buffered fragment loads. Exact reference mask semantics.
// ---------------------------------------------------------------------------
#define AKF(buf) ((buf) * 4096)
#define AVF(buf) (8192 + (buf) * 4096)
#define AQF      16384
#define ATTN_SMEM_BYTES (18432 * 4)    // 73728 B

__global__ __launch_bounds__(64) void attn_kernel(float* __restrict__ out)
{
    extern __shared__ uint32_t smu[];

    const int b    = blockIdx.y;
    const int p    = blockIdx.x;         // 0..31
    const int tid  = threadIdx.x;
    const int w    = tid >> 5;
    const int l    = tid & 31;
    const int qlr  = l >> 2;
    const int qlc  = l & 3;

    const uint32_t* qfb = g_qf + (size_t)b * 131072;
    const uint32_t* kfb = g_kf + (size_t)b * 131072;
    const uint32_t* vfb = g_vf + (size_t)b * 131072;
    float* ob = out + (size_t)b * TT * HH;

    for (int phase = 0; phase < 2; phase++) {
        const int qt = phase ? (63 - p) : p;
        const int qs = qt * 32;
        __syncthreads();    // previous phase fully done with smem

        // Q fragments (2 m-tiles = 8 KB)
        {
            const uint32_t* src = qfb + (uint32_t)(qt * 2) * 1024;
#pragma unroll
            for (int i = 0; i < 8; i++) {
                const int u = tid + i * 64;
                cp_async16(&smu[AQF + u * 4], src + u * 4);
            }
        }
        // key tile 0
        {
#pragma unroll
            for (int i = 0; i < 16; i++) {
                const int u = tid + i * 64;
                cp_async16(&smu[AKF(0) + u * 4], kfb + u * 4);
                cp_async16(&smu[AVF(0) + u * 4], vfb + u * 4);
            }
        }
        CP_COMMIT();

        float oacc[8][4];
#pragma unroll
        for (int nt = 0; nt < 8; nt++)
#pragma unroll
            for (int e = 0; e < 4; e++) oacc[nt][e] = 0.f;
        float m0 = -INFINITY, m1 = -INFINITY, ls0 = 0.f, ls1 = 0.f;
        const int r0 = qs + w * 16 + qlr;
        const int r1 = r0 + 8;

        const int nkb = (qs + 95) >> 6;

        for (int t = 0; t < nkb; t++) {
            const int buf = t & 1;
            if (t + 1 < nkb) {
                const uint32_t* ks_ = kfb + (uint32_t)(t + 1) * 4096;
                const uint32_t* vs_ = vfb + (uint32_t)(t + 1) * 4096;
#pragma unroll
                for (int i = 0; i < 16; i++) {
                    const int u = tid + i * 64;
                    cp_async16(&smu[AKF(buf ^ 1) + u * 4], ks_ + u * 4);
                    cp_async16(&smu[AVF(buf ^ 1) + u * 4], vs_ + u * 4);
                }
                CP_COMMIT();
                CP_WAIT(1);
            } else {
                CP_WAIT(0);
            }
            __syncthreads();     // tile t resident

            // ---- scores: 3-product split bf16 HMMA ----
            float sacc[8][4];
#pragma unroll
            for (int kb = 0; kb < 8; kb++)
#pragma unroll
                for (int e = 0; e < 4; e++) sacc[kb][e] = 0.f;
#pragma unroll
            for (int ks = 0; ks < 4; ks++) {
                uint32_t qh[4], qlo[4];
                *(uint4*)qh  = *(const uint4*)&smu[AQF + ((w * 4 + ks) * 2 + 0) * 128 + l * 4];
                *(uint4*)qlo = *(const uint4*)&smu[AQF + ((w * 4 + ks) * 2 + 1) * 128 + l * 4];
#pragma unroll
                for (int kb = 0; kb < 8; kb++) {
                    U64 kh, kl;
                    kh.u = lds_u64(&smu[AKF(buf) + ((kb * 4 + ks) * 2 + 0) * 64 + l * 2]);
                    kl.u = lds_u64(&smu[AKF(buf) + ((kb * 4 + ks) * 2 + 1) * 64 + l * 2]);
                    mma_bf16(sacc[kb], qh, kh.s);
                    mma_bf16(sacc[kb], qh, kl.s);
                    mma_bf16(sacc[kb], qlo, kh.s);
                }
            }

            // ---- mask + online softmax (fragment-resident) ----
            float mx0 = -INFINITY, mx1 = -INFINITY;
            const int colbase = t * 64 + qlc * 2;
#pragma unroll
            for (int kb = 0; kb < 8; kb++) {
                const int c0 = colbase + kb * 8;
                float s0 = sacc[kb][0] * 0.125f; if (c0 > r0 || s0 == 0.0f) s0 = -INFINITY;
                float s1 = sacc[kb][1] * 0.125f; if (c0 + 1 > r0 || s1 == 0.0f) s1 = -INFINITY;
                float s2 = sacc[kb][2] * 0.125f; if (c0 > r1 || s2 == 0.0f) s2 = -INFINITY;
                float s3 = sacc[kb][3] * 0.125f; if (c0 + 1 > r1 || s3 == 0.0f) s3 = -INFINITY;
                sacc[kb][0] = s0; sacc[kb][1] = s1; sacc[kb][2] = s2; sacc[kb][3] = s3;
                mx0 = fmaxf(mx0, fmaxf(s0, s1));
                mx1 = fmaxf(mx1, fmaxf(s2, s3));
            }
            mx0 = fmaxf(mx0, __shfl_xor_sync(0xffffffffu, mx0, 1));
            mx0 = fmaxf(mx0, __shfl_xor_sync(0xffffffffu, mx0, 2));
            mx1 = fmaxf(mx1, __shfl_xor_sync(0xffffffffu, mx1, 1));
            mx1 = fmaxf(mx1, __shfl_xor_sync(0xffffffffu, mx1, 2));

            const float mn0 = fmaxf(m0, mx0), mn1 = fmaxf(m1, mx1);
            const float f0 = __expf(m0 - mn0), f1 = __expf(m1 - mn1);
            m0 = mn0; m1 = mn1;

            float ps0 = 0.f, ps1 = 0.f;
#pragma unroll
            for (int kb = 0; kb < 8; kb++) {
                const float e0 = __expf(sacc[kb][0] - mn0);
                const float e1 = __expf(sacc[kb][1] - mn0);
                const float e2 = __expf(sacc[kb][2] - mn1);
                const float e3 = __expf(sacc[kb][3] - mn1);
                sacc[kb][0] = e0; sacc[kb][1] = e1; sacc[kb][2] = e2; sacc[kb][3] = e3;
                ps0 += e0 + e1; ps1 += e2 + e3;
            }
            ps0 += __shfl_xor_sync(0xffffffffu, ps0, 1);
            ps0 += __shfl_xor_sync(0xffffffffu, ps0, 2);
            ps1 += __shfl_xor_sync(0xffffffffu, ps1, 1);
            ps1 += __shfl_xor_sync(0xffffffffu, ps1, 2);
            ls0 = ls0 * f0 + ps0;
            ls1 = ls1 * f1 + ps1;

#pragma unroll
            for (int nt = 0; nt < 8; nt++) {
                oacc[nt][0] *= f0; oacc[nt][1] *= f0;
                oacc[nt][2] *= f1; oacc[nt][3] *= f1;
            }

            // ---- P @ V : in-register C->A repack + split, 3-product HMMA ----
#pragma unroll
            for (int kt = 0; kt < 4; kt++) {
                uint32_t ph[4], plo[4];
                split2(sacc[2 * kt][0],     sacc[2 * kt][1],     ph[0], plo[0]);
                split2(sacc[2 * kt][2],     sacc[2 * kt][3],     ph[1], plo[1]);
                split2(sacc[2 * kt + 1][0], sacc[2 * kt + 1][1], ph[2], plo[2]);
                split2(sacc[2 * kt + 1][2], sacc[2 * kt + 1][3], ph[3], plo[3]);
#pragma unroll
                for (int nt = 0; nt < 8; nt++) {
                    U64 vh, vl;
                    vh.u = lds_u64(&smu[AVF(buf) + ((kt * 8 + nt) * 2 + 0) * 64 + l * 2]);
                    vl.u = lds_u64(&smu[AVF(buf) + ((kt * 8 + nt) * 2 + 1) * 64 + l * 2]);
                    mma_bf16(oacc[nt], ph, vh.s);
                    mma_bf16(oacc[nt], ph, vl.s);
                    mma_bf16(oacc[nt], plo, vh.s);
                }
            }
            __syncthreads();     // all warps done with buf before refill
        }

        // ---- epilogue ----
        const float i0 = 1.0f / ls0, i1 = 1.0f / ls1;
#pragma unroll
        for (int nt = 0; nt < 8; nt++) {
            const int d0 = nt * 8 + qlc * 2;
            *(float2*)&ob[(size_t)r0 * HH + d0] =
                make_float2(oacc[nt][0] * i0, oacc[nt][1] * i0);
            *(float2*)&ob[(size_t)r1 * HH + d0] =
                make_float2(oacc[nt][2] * i1, oacc[nt][3] * i1);
        }
    }
}

// ---------------------------------------------------------------------------
extern "C" void kernel_launch(void* const* d_in, const int* in_sizes, int n_in,
                              void* d_out, int out_size)
{
    const float* x  = (const float*)d_in[0];
    const float* Wq = (const float*)d_in[1];
    const float* Wk = (const float*)d_in[2];
    const float* Wv = (const float*)d_in[3];
    float* out = (float*)d_out;

    static int smem_set = 0;
    if (!smem_set) {
        cudaFuncSetAttribute(attn_kernel,
                             cudaFuncAttributeMaxDynamicSharedMemorySize,
                             ATTN_SMEM_BYTES);
        smem_set = 1;
    }

    split_a_kernel<<<4096, 256>>>(x);
    split_b_kernel<<<192, 256>>>(Wq, Wk, Wv);
    gemm_kernel<<<128, 128>>>();
    attn_kernel<<<dim3(32, BB), 64, ATTN_SMEM_BYTES>>>(out);
}

// round 14
// speedup vs baseline: 2.2270x; 1.1879x over previous
#include <cuda_runtime.h>
#include <cuda_bf16.h>
#include <math.h>
#include <stdint.h>

#define BB 4
#define TT 2048
#define CC 1024
#define HH 64
#define NROWS (BB * TT)   // 8192

// x fragments for proj GEMM
__device__ uint32_t g_afrag[512 * 64 * 2 * 128];
__device__ uint32_t g_bfrag[64 * 24 * 2 * 64];
// q/k/v in mma fragment form, produced by gemm epilogue
__device__ uint32_t g_qf[4 * 128 * 4 * 2 * 128];   // [b][mtile][ks][prec][lane*4+r]
__device__ uint32_t g_kf[4 * 256 * 4 * 2 * 64];    // [b][keyblk][ks][prec][lane*2+r]
__device__ uint32_t g_vf[4 * 128 * 8 * 2 * 64];    // [b][keytile][nt][prec][lane*2+r]

typedef unsigned long long ull;
union U64 { ull u; uint32_t s[2]; };

// ---------------- helpers ----------------
__device__ __forceinline__ ull lds_u64(const void* p) {
    uint32_t sa = (uint32_t)__cvta_generic_to_shared(p);
    ull r;
    asm volatile("ld.shared.u64 %0, [%1];" : "=l"(r) : "r"(sa));
    return r;
}
__device__ __forceinline__ void cp_async16(void* smem_dst, const void* gptr) {
    uint32_t sa = (uint32_t)__cvta_generic_to_shared(smem_dst);
    asm volatile("cp.async.cg.shared.global [%0], [%1], 16;" :: "r"(sa), "l"(gptr));
}
#define CP_COMMIT() asm volatile("cp.async.commit_group;")
#define CP_WAIT(n)  asm volatile("cp.async.wait_group %0;" :: "n"(n))
#define PBAR(g)     asm volatile("bar.sync %0, 64;" :: "r"((g) + 1) : "memory")

__device__ __forceinline__ uint32_t pack_bf16x2(float a, float b) {
    __nv_bfloat162 t;
    t.x = __float2bfloat16_rn(a);
    t.y = __float2bfloat16_rn(b);
    return *(uint32_t*)&t;
}
__device__ __forceinline__ void split2(float a, float b, uint32_t& hi, uint32_t& lo) {
    __nv_bfloat16 ha = __float2bfloat16_rn(a);
    __nv_bfloat16 hb = __float2bfloat16_rn(b);
    __nv_bfloat162 th; th.x = ha; th.y = hb;
    hi = *(uint32_t*)&th;
    lo = pack_bf16x2(a - __bfloat162float(ha), b - __bfloat162float(hb));
}
__device__ __forceinline__ void mma_bf16(float* c, const uint32_t* a, const uint32_t* b) {
    asm volatile(
        "mma.sync.aligned.m16n8k16.row.col.f32.bf16.bf16.f32 "
        "{%0,%1,%2,%3}, {%4,%5,%6,%7}, {%8,%9}, {%0,%1,%2,%3};"
        : "+f"(c[0]), "+f"(c[1]), "+f"(c[2]), "+f"(c[3])
        : "r"(a[0]), "r"(a[1]), "r"(a[2]), "r"(a[3]), "r"(b[0]), "r"(b[1]));
}

// ---------------------------------------------------------------------------
// Kernel 0a: x -> bf16 (hi,lo) A-fragments.
// ---------------------------------------------------------------------------
__global__ __launch_bounds__(256) void split_a_kernel(const float* __restrict__ x)
{
    const int unit = blockIdx.x * 8 + (threadIdx.x >> 5);
    const int lane = threadIdx.x & 31;
    const int mt   = unit >> 6;
    const int ks   = unit & 63;
    const uint32_t base = (uint32_t)(mt * 64 + ks) * 256;

#pragma unroll
    for (int r = 0; r < 4; r++) {
        const int m = mt * 16 + (lane >> 2) + ((r & 1) << 3);
        const int k = ks * 16 + ((lane & 3) << 1) + ((r >> 1) << 3);
        const float2 v = *(const float2*)&x[(size_t)m * CC + k];
        uint32_t hi, lo;
        split2(v.x, v.y, hi, lo);
        g_afrag[base + lane * 4 + r]       = hi;
        g_afrag[base + 128 + lane * 4 + r] = lo;
    }
}

// ---------------------------------------------------------------------------
// Kernel 0b: W -> bf16 (hi,lo) B-fragments.
// ---------------------------------------------------------------------------
__global__ __launch_bounds__(256) void split_b_kernel(
    const float* __restrict__ Wq,
    const float* __restrict__ Wk,
    const float* __restrict__ Wv)
{
    const int idx  = blockIdx.x * 256 + threadIdx.x;
    const int lane = idx & 31;
    const int nt   = (idx >> 5) % 24;
    const int ks   = idx / 768;
    const int n    = nt * 8 + (lane >> 2);
    const float* W = (n < 64) ? Wq : (n < 128) ? Wk : Wv;
    const int nc   = n & 63;
    const uint32_t base = (uint32_t)(ks * 24 + nt) * 128;

#pragma unroll
    for (int r = 0; r < 2; r++) {
        const int k = ks * 16 + ((lane & 3) << 1) + (r << 3);
        const float v0 = W[k * HH + nc];
        const float v1 = W[(k + 1) * HH + nc];
        uint32_t hi, lo;
        split2(v0, v1, hi, lo);
        g_bfrag[base + lane * 2 + r]      = hi;
        g_bfrag[base + 64 + lane * 2 + r] = lo;
    }
}

// ---------------------------------------------------------------------------
// Kernel 1: QKV projection via mma.sync; epilogue emits fragment-form q/k/v.
// ---------------------------------------------------------------------------
__global__ __launch_bounds__(128) void gemm_kernel()
{
    __shared__ uint32_t As[2][4 * 256];
    __shared__ uint32_t Bs[2][24 * 128];
    __shared__ float    Vsm[4][16][64];

    const int tid  = threadIdx.x;
    const int w    = tid >> 5;
    const int lane = tid & 31;
    const int mt0  = blockIdx.x * 4;
    const int row0 = blockIdx.x * 64;

    float acc[24][4];
#pragma unroll
    for (int nt = 0; nt < 24; nt++)
#pragma unroll
        for (int e = 0; e < 4; e++) acc[nt][e] = 0.f;

    {
#pragma unroll
        for (int i = 0; i < 2; i++) {
            const int u = tid + i * 128;
            const int chunk = u >> 6;
            const int within = (u & 63) * 4;
            cp_async16(&As[0][chunk * 256 + within],
                       g_afrag + (uint32_t)((mt0 + chunk) * 64 + 0) * 256 + within);
        }
#pragma unroll
        for (int i = 0; i < 6; i++) {
            const int u = tid + i * 128;
            cp_async16(&Bs[0][u * 4], g_bfrag + u * 4);
        }
        CP_COMMIT();
    }

    for (int ks = 0; ks < 64; ks++) {
        const int buf = ks & 1;
        CP_WAIT(0);
        __syncthreads();

        if (ks + 1 < 64) {
#pragma unroll
            for (int i = 0; i < 2; i++) {
                const int u = tid + i * 128;
                const int chunk = u >> 6;
                const int within = (u & 63) * 4;
                cp_async16(&As[buf ^ 1][chunk * 256 + within],
                           g_afrag + (uint32_t)((mt0 + chunk) * 64 + ks + 1) * 256 + within);
            }
#pragma unroll
            for (int i = 0; i < 6; i++) {
                const int u = tid + i * 128;
                cp_async16(&Bs[buf ^ 1][u * 4],
                           g_bfrag + (uint32_t)(ks + 1) * 3072 + u * 4);
            }
            CP_COMMIT();
        }

        uint32_t ah[4], al[4];
        *(uint4*)ah = *(const uint4*)&As[buf][w * 256 + lane * 4];
        *(uint4*)al = *(const uint4*)&As[buf][w * 256 + 128 + lane * 4];

#pragma unroll
        for (int nt = 0; nt < 24; nt++) {
            uint32_t bh[2], bl[2];
            *(uint2*)bh = *(const uint2*)&Bs[buf][nt * 128 + lane * 2];
            *(uint2*)bl = *(const uint2*)&Bs[buf][nt * 128 + 64 + lane * 2];
            mma_bf16(acc[nt], ah, bh);
            mma_bf16(acc[nt], ah, bl);
            mma_bf16(acc[nt], al, bh);
        }
    }

    // ---- epilogue: write fragment-form q/k/v ----
    const int rw  = row0 + w * 16;
    const int bb  = rw >> 11;
    const int mtb = (rw & 2047) >> 4;
    const int kb0 = (rw & 2047) >> 3;
    const int ktb = mtb;
    const int qlr = lane >> 2;
    const int qlc = lane & 3;

#pragma unroll
    for (int ks = 0; ks < 4; ks++) {
        uint32_t h0, l0, h1, l1, h2, l2, h3, l3;
        split2(acc[2 * ks][0],     acc[2 * ks][1],     h0, l0);
        split2(acc[2 * ks][2],     acc[2 * ks][3],     h1, l1);
        split2(acc[2 * ks + 1][0], acc[2 * ks + 1][1], h2, l2);
        split2(acc[2 * ks + 1][2], acc[2 * ks + 1][3], h3, l3);
        const uint32_t base = (uint32_t)(((bb * 128 + mtb) * 4 + ks) * 2) * 128 + lane * 4;
        *(uint4*)&g_qf[base]       = make_uint4(h0, h1, h2, h3);
        *(uint4*)&g_qf[base + 128] = make_uint4(l0, l1, l2, l3);
    }

#pragma unroll
    for (int ks = 0; ks < 4; ks++) {
        uint32_t b0h, b0l, b1h, b1l;
        split2(acc[8 + 2 * ks][0], acc[8 + 2 * ks][1], b0h, b0l);
        split2(acc[9 + 2 * ks][0], acc[9 + 2 * ks][1], b1h, b1l);
        uint32_t base = (uint32_t)(((bb * 256 + kb0) * 4 + ks) * 2) * 64 + lane * 2;
        *(uint2*)&g_kf[base]      = make_uint2(b0h, b1h);
        *(uint2*)&g_kf[base + 64] = make_uint2(b0l, b1l);
        split2(acc[8 + 2 * ks][2], acc[8 + 2 * ks][3], b0h, b0l);
        split2(acc[9 + 2 * ks][2], acc[9 + 2 * ks][3], b1h, b1l);
        base = (uint32_t)(((bb * 256 + kb0 + 1) * 4 + ks) * 2) * 64 + lane * 2;
        *(uint2*)&g_kf[base]      = make_uint2(b0h, b1h);
        *(uint2*)&g_kf[base + 64] = make_uint2(b0l, b1l);
    }

#pragma unroll
    for (int dt = 0; dt < 8; dt++) {
        const int d0 = dt * 8 + qlc * 2;
        Vsm[w][qlr][d0]         = acc[16 + dt][0];
        Vsm[w][qlr][d0 + 1]     = acc[16 + dt][1];
        Vsm[w][qlr + 8][d0]     = acc[16 + dt][2];
        Vsm[w][qlr + 8][d0 + 1] = acc[16 + dt][3];
    }
    __syncwarp();
#pragma unroll
    for (int nt = 0; nt < 8; nt++) {
#pragma unroll
        for (int r = 0; r < 2; r++) {
            const int kl_ = qlc * 2 + r * 8;
            const int dd  = nt * 8 + qlr;
            uint32_t h, lo;
            split2(Vsm[w][kl_][dd], Vsm[w][kl_ + 1][dd], h, lo);
            const uint32_t base = (uint32_t)(((bb * 128 + ktb) * 8 + nt) * 2) * 64 + lane * 2 + r;
            g_vf[base]      = h;
            g_vf[base + 64] = lo;
        }
    }
}

// ---------------------------------------------------------------------------
// Kernel 2: causal attention, all-HMMA, key-parity split across 4 warps.
// 128 blocks (32 pairs x 4 batches) x 128 threads. Phases qt = p, 63-p.
// Warp w: m16 tile (w&1), key parity (w>>1). Each parity owns K/V double
// buffers + named barrier; end-of-phase split-KV merge via smem staging.
// ---------------------------------------------------------------------------
#define KBUF(g, buf) (((g) * 2 + (buf)) * 4096)
#define VBUF(g, buf) (16384 + ((g) * 2 + (buf)) * 4096)
#define AQF 32768
#define ATTN_SMEM_BYTES (34816 * 4)    // 139264 B

__global__ __launch_bounds__(128) void attn_kernel(float* __restrict__ out)
{
    extern __shared__ uint32_t smu[];

    const int b    = blockIdx.y;
    const int p    = blockIdx.x;         // 0..31
    const int tid  = threadIdx.x;
    const int w    = tid >> 5;
    const int l    = tid & 31;
    const int tile = w & 1;              // m16 tile within the 32-row q-tile
    const int g    = w >> 1;             // key parity
    const int lt   = tid & 63;           // thread index within parity group
    const int qlr  = l >> 2;
    const int qlc  = l & 3;

    const uint32_t* qfb = g_qf + (size_t)b * 131072;
    const uint32_t* kfb = g_kf + (size_t)b * 131072;
    const uint32_t* vfb = g_vf + (size_t)b * 131072;
    float* ob = out + (size_t)b * TT * HH;

    for (int phase = 0; phase < 2; phase++) {
        const int qt = phase ? (63 - p) : p;
        const int qs = qt * 32;
        __syncthreads();    // previous phase fully done with smem (incl. merge)

        const int nkb = (qs + 95) >> 6;

        // Q fragments (8 KB, all threads)
        {
            const uint32_t* src = qfb + (uint32_t)(qt * 2) * 1024;
#pragma unroll
            for (int i = 0; i < 4; i++) {
                const int u = tid + i * 128;
                cp_async16(&smu[AQF + u * 4], src + u * 4);
            }
        }
        // parity's first key tile (t = g), if any
        if (g < nkb) {
            const uint32_t* ks_ = kfb + (uint32_t)g * 4096;
            const uint32_t* vs_ = vfb + (uint32_t)g * 4096;
#pragma unroll
            for (int i = 0; i < 16; i++) {
                const int u = lt + i * 64;
                cp_async16(&smu[KBUF(g, 0) + u * 4], ks_ + u * 4);
                cp_async16(&smu[VBUF(g, 0) + u * 4], vs_ + u * 4);
            }
        }
        CP_COMMIT();
        CP_WAIT(0);
        __syncthreads();

        float oacc[8][4];
#pragma unroll
        for (int nt = 0; nt < 8; nt++)
#pragma unroll
            for (int e = 0; e < 4; e++) oacc[nt][e] = 0.f;
        float m0 = -INFINITY, m1 = -INFINITY, ls0 = 0.f, ls1 = 0.f;
        const int r0 = qs + tile * 16 + qlr;
        const int r1 = r0 + 8;

        for (int t = g; t < nkb; t += 2) {
            const int buf = (t >> 1) & 1;
            if (t + 2 < nkb) {
                const uint32_t* ks_ = kfb + (uint32_t)(t + 2) * 4096;
                const uint32_t* vs_ = vfb + (uint32_t)(t + 2) * 4096;
#pragma unroll
                for (int i = 0; i < 16; i++) {
                    const int u = lt + i * 64;
                    cp_async16(&smu[KBUF(g, buf ^ 1) + u * 4], ks_ + u * 4);
                    cp_async16(&smu[VBUF(g, buf ^ 1) + u * 4], vs_ + u * 4);
                }
                CP_COMMIT();
            }

            // ---- scores: 3-product split bf16 HMMA ----
            float sacc[8][4];
#pragma unroll
            for (int kb = 0; kb < 8; kb++)
#pragma unroll
                for (int e = 0; e < 4; e++) sacc[kb][e] = 0.f;
#pragma unroll
            for (int ks = 0; ks < 4; ks++) {
                uint32_t qh[4], qlo[4];
                *(uint4*)qh  = *(const uint4*)&smu[AQF + ((tile * 4 + ks) * 2 + 0) * 128 + l * 4];
                *(uint4*)qlo = *(const uint4*)&smu[AQF + ((tile * 4 + ks) * 2 + 1) * 128 + l * 4];
#pragma unroll
                for (int kb = 0; kb < 8; kb++) {
                    U64 kh, kl;
                    kh.u = lds_u64(&smu[KBUF(g, buf) + ((kb * 4 + ks) * 2 + 0) * 64 + l * 2]);
                    kl.u = lds_u64(&smu[KBUF(g, buf) + ((kb * 4 + ks) * 2 + 1) * 64 + l * 2]);
                    mma_bf16(sacc[kb], qh, kh.s);
                    mma_bf16(sacc[kb], qh, kl.s);
                    mma_bf16(sacc[kb], qlo, kh.s);
                }
            }

            // ---- mask + online softmax ----
            float mx0 = -INFINITY, mx1 = -INFINITY;
            const int colbase = t * 64 + qlc * 2;
#pragma unroll
            for (int kb = 0; kb < 8; kb++) {
                const int c0 = colbase + kb * 8;
                float s0 = sacc[kb][0] * 0.125f; if (c0 > r0 || s0 == 0.0f) s0 = -INFINITY;
                float s1 = sacc[kb][1] * 0.125f; if (c0 + 1 > r0 || s1 == 0.0f) s1 = -INFINITY;
                float s2 = sacc[kb][2] * 0.125f; if (c0 > r1 || s2 == 0.0f) s2 = -INFINITY;
                float s3 = sacc[kb][3] * 0.125f; if (c0 + 1 > r1 || s3 == 0.0f) s3 = -INFINITY;
                sacc[kb][0] = s0; sacc[kb][1] = s1; sacc[kb][2] = s2; sacc[kb][3] = s3;
                mx0 = fmaxf(mx0, fmaxf(s0, s1));
                mx1 = fmaxf(mx1, fmaxf(s2, s3));
            }
            mx0 = fmaxf(mx0, __shfl_xor_sync(0xffffffffu, mx0, 1));
            mx0 = fmaxf(mx0, __shfl_xor_sync(0xffffffffu, mx0, 2));
            mx1 = fmaxf(mx1, __shfl_xor_sync(0xffffffffu, mx1, 1));
            mx1 = fmaxf(mx1, __shfl_xor_sync(0xffffffffu, mx1, 2));

            const float mn0 = fmaxf(m0, mx0), mn1 = fmaxf(m1, mx1);
            const float f0 = __expf(m0 - mn0), f1 = __expf(m1 - mn1);
            m0 = mn0; m1 = mn1;

            float ps0 = 0.f, ps1 = 0.f;
#pragma unroll
            for (int kb = 0; kb < 8; kb++) {
                const float e0 = __expf(sacc[kb][0] - mn0);
                const float e1 = __expf(sacc[kb][1] - mn0);
                const float e2 = __expf(sacc[kb][2] - mn1);
                const float e3 = __expf(sacc[kb][3] - mn1);
                sacc[kb][0] = e0; sacc[kb][1] = e1; sacc[kb][2] = e2; sacc[kb][3] = e3;
                ps0 += e0 + e1; ps1 += e2 + e3;
            }
            ps0 += __shfl_xor_sync(0xffffffffu, ps0, 1);
            ps0 += __shfl_xor_sync(0xffffffffu, ps0, 2);
            ps1 += __shfl_xor_sync(0xffffffffu, ps1, 1);
            ps1 += __shfl_xor_sync(0xffffffffu, ps1, 2);
            ls0 = ls0 * f0 + ps0;
            ls1 = ls1 * f1 + ps1;

#pragma unroll
            for (int nt = 0; nt < 8; nt++) {
                oacc[nt][0] *= f0; oacc[nt][1] *= f0;
                oacc[nt][2] *= f1; oacc[nt][3] *= f1;
            }

            // ---- P @ V ----
#pragma unroll
            for (int kt = 0; kt < 4; kt++) {
                uint32_t ph[4], plo[4];
                split2(sacc[2 * kt][0],     sacc[2 * kt][1],     ph[0], plo[0]);
                split2(sacc[2 * kt][2],     sacc[2 * kt][3],     ph[1], plo[1]);
                split2(sacc[2 * kt + 1][0], sacc[2 * kt + 1][1], ph[2], plo[2]);
                split2(sacc[2 * kt + 1][2], sacc[2 * kt + 1][3], ph[3], plo[3]);
#pragma unroll
                for (int nt = 0; nt < 8; nt++) {
                    U64 vh, vl;
                    vh.u = lds_u64(&smu[VBUF(g, buf) + ((kt * 8 + nt) * 2 + 0) * 64 + l * 2]);
                    vl.u = lds_u64(&smu[VBUF(g, buf) + ((kt * 8 + nt) * 2 + 1) * 64 + l * 2]);
                    mma_bf16(oacc[nt], ph, vh.s);
                    mma_bf16(oacc[nt], ph, vl.s);
                    mma_bf16(oacc[nt], plo, vh.s);
                }
            }

            if (t + 2 < nkb) CP_WAIT(0);
            PBAR(g);             // both warps of this parity done with buffers
        }

        // ---- split-KV merge across parities ----
        __syncthreads();         // all compute done; smem buffers reusable
        float* stg = (float*)smu;
        if (g == 1) {
            float* sl = stg + (tile * 32 + l) * 36;
#pragma unroll
            for (int nt = 0; nt < 8; nt++)
#pragma unroll
                for (int e = 0; e < 4; e++) sl[nt * 4 + e] = oacc[nt][e];
            sl[32] = m0; sl[33] = m1; sl[34] = ls0; sl[35] = ls1;
        }
        __syncthreads();
        if (g == 0) {
            const float* sl = stg + (tile * 32 + l) * 36;
            const float mB0 = sl[32], mB1 = sl[33], lsB0 = sl[34], lsB1 = sl[35];
            const float mm0 = fmaxf(m0, mB0), mm1 = fmaxf(m1, mB1);
            const float fA0 = __expf(m0 - mm0),  fB0 = __expf(mB0 - mm0);
            const float fA1 = __expf(m1 - mm1),  fB1 = __expf(mB1 - mm1);
            const float inv0 = 1.0f / (ls0 * fA0 + lsB0 * fB0);
            const float inv1 = 1.0f / (ls1 * fA1 + lsB1 * fB1);
#pragma unroll
            for (int nt = 0; nt < 8; nt++) {
                const int d0 = nt * 8 + qlc * 2;
                const float o0 = (oacc[nt][0] * fA0 + sl[nt * 4 + 0] * fB0) * inv0;
                const float o1 = (oacc[nt][1] * fA0 + sl[nt * 4 + 1] * fB0) * inv0;
                const float o2 = (oacc[nt][2] * fA1 + sl[nt * 4 + 2] * fB1) * inv1;
                const float o3 = (oacc[nt][3] * fA1 + sl[nt * 4 + 3] * fB1) * inv1;
                *(float2*)&ob[(size_t)r0 * HH + d0] = make_float2(o0, o1);
                *(float2*)&ob[(size_t)r1 * HH + d0] = make_float2(o2, o3);
            }
        }
    }
}

// ---------------------------------------------------------------------------
extern "C" void kernel_launch(void* const* d_in, const int* in_sizes, int n_in,
                              void* d_out, int out_size)
{
    const float* x  = (const float*)d_in[0];
    const float* Wq = (const float*)d_in[1];
    const float* Wk = (const float*)d_in[2];
    const float* Wv = (const float*)d_in[3];
    float* out = (float*)d_out;

    static int smem_set = 0;
    if (!smem_set) {
        cudaFuncSetAttribute(attn_kernel,
                             cudaFuncAttributeMaxDynamicSharedMemorySize,
                             ATTN_SMEM_BYTES);
        smem_set = 1;
    }

    split_a_kernel<<<4096, 256>>>(x);
    split_b_kernel<<<192, 256>>>(Wq, Wk, Wv);
    gemm_kernel<<<128, 128>>>();
    attn_kernel<<<dim3(32, BB), 128, ATTN_SMEM_BYTES>>>(out);
}